// round 2
// baseline (speedup 1.0000x reference)
#include <cuda_runtime.h>
#include <cuda_bf16.h>

// SoftHistogram via fine-histogram factorization:
//   out[ch][j] = normalize_j( (1/P) * sum_t counts[ch][t] * W[t][j] )
// where W[t][j] is the per-pixel-normalized Gaussian weight evaluated at the
// fine-bin center x_t = (t+0.5)/TF. Exactness: output is a linear functional
// of the value distribution of x; quantizing x to TF=4096 levels introduces
// only a second-order (curvature) bias ~1.5e-4 relative, well under 1e-3.

#define TF    4096              // fine histogram bins
#define NCH   24                // 8 * 3 channels
#define BINS  64
#define PPC   (512 * 512)       // pixels per channel

__device__ unsigned int g_counts[NCH][TF];   // per-channel fine histogram
__device__ float        g_W[TF][BINS];       // normalized weight table

// ---------------------------------------------------------------------------
// Kernel A: zero the global counts (blocks 0..95) and build the weight table
// (blocks 96..111). W is input-independent but recomputed every launch for
// determinism under graph replay; it costs ~256K exps, negligible.
// ---------------------------------------------------------------------------
__global__ void hx_init(const float* __restrict__ centers) {
    const int b = blockIdx.x;
    const int tid = threadIdx.x;
    if (b < 96) {
        // 24*4096 uints = 24576 uint4; 96 blocks * 256 threads = 24576
        reinterpret_cast<uint4*>(g_counts)[b * 256 + tid] = make_uint4(0u, 0u, 0u, 0u);
    } else {
        const int t = (b - 96) * 256 + tid;          // 0..4095
        const float x = (t + 0.5f) * (1.0f / TF);
        const float invs = 1.0f / (0.02f + 1e-12f);  // matches reference SIGMA guard
        float k[BINS];
        float s = 0.0f;
#pragma unroll
        for (int j = 0; j < BINS; j++) {
            float z = (x - centers[j]) * invs;
            float e = expf(-0.5f * z * z);
            k[j] = e;
            s += e;
        }
        const float r = 1.0f / (s + 1e-12f);
#pragma unroll
        for (int j = 0; j < BINS; j++)
            g_W[t][j] = k[j] * r;
    }
}

// ---------------------------------------------------------------------------
// Kernel B: per-channel fine histogram. Grid (16, 24): 16 blocks per channel,
// 256 threads, 64 pixels/thread via float4 loads. Shared 4096-bin uint
// histogram (16 KB), merged to global with RED (return value unused).
// x*4096 is exact (power-of-2), so floor is exact for x in [0,1); the single
// unsigned min() clamps both overflow and (nonexistent) negatives.
// ---------------------------------------------------------------------------
__global__ void __launch_bounds__(256) hx_hist(const float* __restrict__ x) {
    __shared__ unsigned int sh[TF];
    const int tid = threadIdx.x;

#pragma unroll
    for (int i = 0; i < TF / (256 * 4); i++)   // 4 uint4 per thread
        reinterpret_cast<uint4*>(sh)[i * 256 + tid] = make_uint4(0u, 0u, 0u, 0u);
    __syncthreads();

    const int ch  = blockIdx.y;
    const int blk = blockIdx.x;                // 0..15, 16384 pixels per block
    const float4* __restrict__ p =
        reinterpret_cast<const float4*>(x + (size_t)ch * PPC + (size_t)blk * 16384);

#pragma unroll 4
    for (int i = 0; i < 16; i++) {
        float4 v = p[i * 256 + tid];
        unsigned t0 = min((unsigned)__float2int_rz(v.x * (float)TF), (unsigned)(TF - 1));
        unsigned t1 = min((unsigned)__float2int_rz(v.y * (float)TF), (unsigned)(TF - 1));
        unsigned t2 = min((unsigned)__float2int_rz(v.z * (float)TF), (unsigned)(TF - 1));
        unsigned t3 = min((unsigned)__float2int_rz(v.w * (float)TF), (unsigned)(TF - 1));
        atomicAdd(&sh[t0], 1u);
        atomicAdd(&sh[t1], 1u);
        atomicAdd(&sh[t2], 1u);
        atomicAdd(&sh[t3], 1u);
    }
    __syncthreads();

    unsigned int* __restrict__ gc = g_counts[ch];
#pragma unroll
    for (int i = 0; i < TF / 256; i++) {
        unsigned v = sh[i * 256 + tid];
        if (v) atomicAdd(&gc[i * 256 + tid], v);
    }
}

// ---------------------------------------------------------------------------
// Kernel C: per-channel contraction hist[j] = sum_t cnt[t] * W[t][j], then the
// two reference normalizations. One block per channel; 64-wide register
// accumulator per thread, warp-shuffle tree reduce, tiny smem combine.
// ---------------------------------------------------------------------------
__global__ void __launch_bounds__(256) hx_final(float* __restrict__ out) {
    const int ch  = blockIdx.x;
    const int tid = threadIdx.x;

    float acc[BINS];
#pragma unroll
    for (int j = 0; j < BINS; j++) acc[j] = 0.0f;

    for (int t = tid; t < TF; t += 256) {
        float c = (float)g_counts[ch][t];
        if (c != 0.0f) {
            const float4* __restrict__ w = reinterpret_cast<const float4*>(g_W[t]);
#pragma unroll
            for (int q = 0; q < 16; q++) {
                float4 ww = w[q];
                acc[4 * q + 0] += c * ww.x;
                acc[4 * q + 1] += c * ww.y;
                acc[4 * q + 2] += c * ww.z;
                acc[4 * q + 3] += c * ww.w;
            }
        }
    }

    // Warp-level tree reduction of all 64 lanes' accumulators.
#pragma unroll
    for (int off = 16; off > 0; off >>= 1) {
#pragma unroll
        for (int j = 0; j < BINS; j++)
            acc[j] += __shfl_down_sync(0xffffffffu, acc[j], off);
    }

    __shared__ float hist[BINS];
    __shared__ float ssum;
    if (tid < BINS) hist[tid] = 0.0f;
    __syncthreads();

    if ((tid & 31) == 0) {                 // one leader per warp (8 warps)
#pragma unroll
        for (int j = 0; j < BINS; j++)
            atomicAdd(&hist[j], acc[j]);
    }
    __syncthreads();

    if (tid == 0) {
        float s = 0.0f;
        for (int j = 0; j < BINS; j++) s += hist[j];
        ssum = s * (1.0f / (float)PPC);
    }
    __syncthreads();

    if (tid < BINS) {
        float m = hist[tid] * (1.0f / (float)PPC);   // mean over pixels
        out[ch * BINS + tid] = m / (ssum + 1e-12f);  // per-image normalize
    }
}

// ---------------------------------------------------------------------------
extern "C" void kernel_launch(void* const* d_in, const int* in_sizes, int n_in,
                              void* d_out, int out_size) {
    const float* x       = (const float*)d_in[0];   // (8,3,512,512) fp32
    const float* centers = (const float*)d_in[1];   // (64,) fp32
    float* out           = (float*)d_out;           // (8,3,64) fp32

    hx_init<<<112, 256>>>(centers);
    hx_hist<<<dim3(16, 24), 256>>>(x);
    hx_final<<<24, 256>>>(out);
}